// round 1
// baseline (speedup 1.0000x reference)
#include <cuda_runtime.h>
#include <stdint.h>

// ChannelPair2D: out[p, k] = x[p, i_k] * x[p, j_k], pairs (i,j) i<j in row-major
// triu order. C=64 -> 2016 pairs. B*H*W = 65536 pixels.
// Pure HBM-write-bound streaming kernel: ~504 MiB output.

#define C_CH    64
#define NPAIR   2016      // C*(C-1)/2
#define NP4     504       // NPAIR/4
#define TPB     256
#define PPB     8         // pixels per block

__global__ __launch_bounds__(TPB)
void channelpair_kernel(const float* __restrict__ x,
                        float* __restrict__ out,
                        int npix) {
    __shared__ float  sx[PPB * C_CH];     // 2 KB
    __shared__ uchar2 sp[NPAIR];          // 4 KB pair-index table

    const int tid = threadIdx.x;

    // ---- Build (i,j) pair table once per block (amortized over PPB pixels).
    // off(i) = i*(127-i)/2 ; k in [off(i), off(i+1)) -> j = i+1 + k - off(i)
    for (int k = tid; k < NPAIR; k += TPB) {
        int i = (int)((127.0 - sqrt(127.0 * 127.0 - 8.0 * (double)k)) * 0.5);
        if (i < 0) i = 0;
        if (i > 62) i = 62;
        while (i > 0 && k < i * (127 - i) / 2) --i;
        while (k >= (i + 1) * (126 - i) / 2) ++i;
        int j = i + 1 + (k - i * (127 - i) / 2);
        sp[k] = make_uchar2((unsigned char)i, (unsigned char)j);
    }

    // ---- Load PPB pixel vectors (PPB*64 floats = PPB*16 float4), coalesced.
    const int pix0 = blockIdx.x * PPB;
    {
        const float4* __restrict__ xin = (const float4*)(x + (size_t)pix0 * C_CH);
        float4* sx4 = (float4*)sx;
        #pragma unroll
        for (int t = tid; t < PPB * (C_CH / 4); t += TPB) {
            // guard for a possible partial last block
            int pix = pix0 + t / (C_CH / 4);
            if (pix < npix) sx4[t] = xin[t];
        }
    }
    __syncthreads();

    // ---- Emit 504 float4 per pixel (2016 floats, contiguous -> coalesced STG.128)
    #pragma unroll 1
    for (int p = 0; p < PPB; ++p) {
        const int pix = pix0 + p;
        if (pix >= npix) break;
        const float* __restrict__ xv = sx + p * C_CH;
        float4* __restrict__ o4 = (float4*)(out + (size_t)pix * NPAIR);
        #pragma unroll
        for (int it = 0; it < 2; ++it) {
            const int k4 = tid + it * TPB;
            if (k4 < NP4) {
                const int k = 4 * k4;
                const uchar2 q0 = sp[k + 0];
                const uchar2 q1 = sp[k + 1];
                const uchar2 q2 = sp[k + 2];
                const uchar2 q3 = sp[k + 3];
                float4 r;
                r.x = xv[q0.x] * xv[q0.y];
                r.y = xv[q1.x] * xv[q1.y];
                r.z = xv[q2.x] * xv[q2.y];
                r.w = xv[q3.x] * xv[q3.y];
                o4[k4] = r;
            }
        }
    }
}

extern "C" void kernel_launch(void* const* d_in, const int* in_sizes, int n_in,
                              void* d_out, int out_size) {
    const float* x = (const float*)d_in[0];
    float* out = (float*)d_out;

    const int npix = in_sizes[0] / C_CH;          // 65536
    const int nblk = (npix + PPB - 1) / PPB;      // 8192

    channelpair_kernel<<<nblk, TPB>>>(x, out, npix);
}

// round 2
// speedup vs baseline: 4.6452x; 4.6452x over previous
#include <cuda_runtime.h>
#include <stdint.h>

// ChannelPair2D: out[p, k] = x[p, i_k] * x[p, j_k], (i,j) i<j row-major triu.
// C=64 -> 2016 pairs, 65536 pixels. HBM-write-bound target (~504 MiB out).

#define C_CH    64
#define NPAIR   2016
#define NQ      504       // NPAIR/4 quads
#define TPB     256
#define PPB     8         // pixels per block

__global__ __launch_bounds__(TPB)
void channelpair_kernel(const float* __restrict__ x,
                        float* __restrict__ out,
                        int npix) {
    // Shifted replicas: B[s][p][c] = x_p[c+s]  (s=0..3). Enables aligned
    // conflict-free LDS.128 of x[j..j+3] at B[j&3][p][j&~3].
    __shared__ __align__(16) float B[4][PPB][C_CH];   // 8 KB
    __shared__ uint2 qt[NQ];                          // 4 KB: 4 packed (i,j) pairs per quad

    const int tid  = threadIdx.x;
    const int pix0 = blockIdx.x * PPB;

    // ---- Per-quad pair table (cheap: MUFU sqrtf + integer fixup) ----
    for (int q = tid; q < NQ; q += TPB) {
        const int k = 4 * q;
        int i = (int)((127.0f - sqrtf(16129.0f - 8.0f * (float)k)) * 0.5f);
        i = (i < 0) ? 0 : ((i > 62) ? 62 : i);
        while (i > 0  && k <  i * (127 - i) / 2)       --i;
        while (i < 62 && k >= (i + 1) * (126 - i) / 2) ++i;
        int j = i + 1 + (k - i * (127 - i) / 2);

        unsigned a, b;
        int ii = i, jj = j;
        a  = (unsigned)ii | ((unsigned)jj << 8);
        if (++jj > 63) { ++ii; jj = ii + 1; }
        a |= ((unsigned)ii << 16) | ((unsigned)jj << 24);
        if (++jj > 63) { ++ii; jj = ii + 1; }
        b  = (unsigned)ii | ((unsigned)jj << 8);
        if (++jj > 63) { ++ii; jj = ii + 1; }
        b |= ((unsigned)ii << 16) | ((unsigned)jj << 24);
        qt[q] = make_uint2(a, b);
    }

    // ---- Load PPB pixel vectors into B[0] (coalesced float4) ----
    {
        float4* dst = (float4*)&B[0][0][0];
        const float4* src = (const float4*)(x + (size_t)pix0 * C_CH);
        #pragma unroll
        for (int t = tid; t < PPB * (C_CH / 4); t += TPB) {
            const int pix = pix0 + t / (C_CH / 4);
            dst[t] = (pix < npix) ? src[t] : make_float4(0.f, 0.f, 0.f, 0.f);
        }
    }
    __syncthreads();

    // ---- Build shifted replicas B[1..3] (conflict-free, 6 elems/thread) ----
    for (int t = tid; t < 3 * PPB * C_CH; t += TPB) {
        const int s = 1 + t / (PPB * C_CH);
        const int r = t % (PPB * C_CH);
        const int p = r / C_CH;
        const int c = r % C_CH;
        const int src_c = (c + s > 63) ? 63 : (c + s);
        B[s][p][c] = B[0][p][src_c];
    }
    __syncthreads();

    // ---- Main: 1 quad (float4) per thread-iter, coalesced STG.128 ----
    #pragma unroll 1
    for (int p = 0; p < PPB; ++p) {
        const int pix = pix0 + p;
        if (pix >= npix) break;
        float4* __restrict__ o4 = (float4*)(out + (size_t)pix * NPAIR);
        const float* __restrict__ x0 = &B[0][p][0];

        #pragma unroll
        for (int it = 0; it < 2; ++it) {
            const int q = tid + it * TPB;
            if (q < NQ) {
                const uint2 t = qt[q];
                const int i0 = t.x & 255;
                const int j0 = (t.x >> 8) & 255;
                const int i3 = (t.y >> 16) & 255;
                float4 r;
                if (i0 == i3) {
                    // Run-interior quad: same i, j..j+3 consecutive.
                    const float xi = x0[i0];
                    const int s = j0 & 3, a = j0 & ~3;
                    const float4 v = *(const float4*)&B[s][p][a];
                    r.x = xi * v.x; r.y = xi * v.y;
                    r.z = xi * v.z; r.w = xi * v.w;
                } else {
                    // Boundary quad: unpack all 4 pairs.
                    const int i1 = (t.x >> 16) & 255, j1 = (t.x >> 24) & 255;
                    const int i2 = t.y & 255,         j2 = (t.y >> 8) & 255;
                    const int j3 = (t.y >> 24) & 255;
                    r.x = x0[i0] * x0[j0];
                    r.y = x0[i1] * x0[j1];
                    r.z = x0[i2] * x0[j2];
                    r.w = x0[i3] * x0[j3];
                }
                o4[q] = r;
            }
        }
    }
}

extern "C" void kernel_launch(void* const* d_in, const int* in_sizes, int n_in,
                              void* d_out, int out_size) {
    const float* x = (const float*)d_in[0];
    float* out = (float*)d_out;

    const int npix = in_sizes[0] / C_CH;          // 65536
    const int nblk = (npix + PPB - 1) / PPB;      // 8192

    channelpair_kernel<<<nblk, TPB>>>(x, out, npix);
}